// round 14
// baseline (speedup 1.0000x reference)
#include <cuda_runtime.h>
#include <math.h>

#define BB 2
#define CC 64
#define HH 64
#define WW 64
#define LL 4096
#define MM (BB*LL)          // 8192 tokens
#define DIN 128             // D_INNER
#define DST 64              // D_STATE
#define DTR 4               // DT_RANK
#define HID 256             // HIDDEN
#define KCONV 576           // 64*9
#define NCH 16              // chunks

// ------------------------- scratch buffers (device globals) -------------------------
__device__ float g_c1   [BB*CC*HH*WW];      // conv1 out NCHW
__device__ float g_t    [MM*CC];            // tokens (B,L,64), residual accumulator
__device__ float g_xz   [MM*2*DIN];         // in_proj out: [:,:128]=xin, [:,128:]=z
__device__ float g_xc   [MM*DIN];           // conv1d+silu out (row major)
__device__ float g_xc4  [MM*DIN];           // same, blocked (B, L/4, 128, 4)
__device__ float g_Brow [MM*DST];           // B row-major (m,64)
__device__ float g_Crow [MM*DST];           // C row-major (m,64)
__device__ float g_d4   [MM*DIN];           // delta blocked (B, L/4, 128, 4)
__device__ float g_P    [BB*NCH*DIN*DST];   // per-chunk decay
__device__ float g_S    [BB*NCH*DIN*DST];   // per-chunk local final state
__device__ float g_Hi   [BB*NCH*DIN*DST];   // per-chunk initial state
__device__ float g_yg   [MM*DIN];           // gated y
__device__ float g_h1   [MM*HID];           // fc1 out
__device__ float g_g    [MM*HID];           // dwconv+gelu out
__device__ float g_w1t  [KCONV*CC];         // conv1 weight reordered [(seg,ci)][co]
__device__ float g_w2t  [KCONV*CC];         // conv2 weight reordered
__device__ float g_wcat [256*DIN];          // [B rows | C rows | dtw@xprojw_dt] (256 x 128)

// ------------------------- merged weight prep -------------------------
__global__ void prep_kernel(const float* __restrict__ w1, const float* __restrict__ w2,
                            const float* __restrict__ xprojw, const float* __restrict__ dtw){
    int i = blockIdx.x*256 + threadIdx.x;
    if (i < KCONV*CC){
        int k = i >> 6, co = i & 63;
        int seg = k >> 6, ci = k & 63;
        int src = co*KCONV + ci*9 + seg;
        g_w1t[i] = w1[src];
        g_w2t[i] = w2[src];
    }
    if (i < 256*DIN){
        int n = i >> 7, k = i & 127;
        float v;
        if (n < 64)       v = xprojw[(4 + n)*DIN + k];
        else if (n < 128) v = xprojw[(68 + n - 64)*DIN + k];
        else {
            int dd = n - 128;
            v = dtw[dd*4+0]*xprojw[0*DIN + k] + dtw[dd*4+1]*xprojw[1*DIN + k]
              + dtw[dd*4+2]*xprojw[2*DIN + k] + dtw[dd*4+3]*xprojw[3*DIN + k];
        }
        g_wcat[i] = v;
    }
}

// ------------------------- implicit-GEMM 3x3 conv, 128-thread 32x64 tiles, double-buffered -------------------------
template<int MODE>
__global__ void __launch_bounds__(128) conv3_kernel(const float* __restrict__ in,
                                                    const float* __restrict__ wt,
                                                    const float* __restrict__ bias){
    __shared__ float As[2][32][36];                   // [buf][k(ci)][m(w)]
    __shared__ __align__(16) float Bs[2][32*68];
    int blk = blockIdx.x;
    int b = blk >> 7, rest = blk & 127;
    int hh = rest >> 1, wh = rest & 1;                // w half
    int t = threadIdx.x, tx = t & 15, ty = t >> 4;    // ty 0..7 (w quads), tx 0..15 (co quads)
    float acc[4][4] = {};
    int aw = t & 31, ci0 = t >> 5;                    // A fill: w=aw, ci = ci0 + 4*jj (jj 0..7)
    int bk = t >> 4, bcg = (t & 15) << 2;             // B fill: rows bk + 8*r (r 0..3)
    float ar[8]; float4 br[4];

    #define CPREF(cc) { \
        int seg = (cc) >> 1, kh = (cc) & 1; \
        int ky = seg / 3, kx = seg - ky*3; \
        int y = hh + ky - 1, x = (wh<<5) + aw + kx - 1; \
        bool ok = (y >= 0) && (y < 64) && (x >= 0) && (x < 64); \
        const float* src = in + (((size_t)b << 18) + ((size_t)(kh*32 + ci0) << 12) + (y << 6) + x); \
        _Pragma("unroll") \
        for (int jj = 0; jj < 8; jj++) ar[jj] = ok ? src[(size_t)(jj*4) << 12] : 0.f; \
        const float* wp = wt + (size_t)(seg*64 + kh*32 + bk)*64 + bcg; \
        _Pragma("unroll") \
        for (int r = 0; r < 4; r++) br[r] = *(const float4*)(wp + (size_t)(r*8)*64); }

    CPREF(0);
    int cur = 0;
    #pragma unroll 1
    for (int cc = 0; cc < 18; cc++){
        #pragma unroll
        for (int jj = 0; jj < 8; jj++) As[cur][ci0 + jj*4][aw] = ar[jj];
        #pragma unroll
        for (int r = 0; r < 4; r++) *(float4*)&Bs[cur][(bk + r*8)*68 + bcg] = br[r];
        __syncthreads();
        if (cc < 17) CPREF(cc+1);
        #pragma unroll
        for (int k = 0; k < 32; k++){
            float4 av = *(const float4*)&As[cur][k][ty<<2];
            float4 bv = *(const float4*)&Bs[cur][k*68 + (tx<<2)];
            acc[0][0] = fmaf(av.x,bv.x,acc[0][0]); acc[0][1] = fmaf(av.x,bv.y,acc[0][1]);
            acc[0][2] = fmaf(av.x,bv.z,acc[0][2]); acc[0][3] = fmaf(av.x,bv.w,acc[0][3]);
            acc[1][0] = fmaf(av.y,bv.x,acc[1][0]); acc[1][1] = fmaf(av.y,bv.y,acc[1][1]);
            acc[1][2] = fmaf(av.y,bv.z,acc[1][2]); acc[1][3] = fmaf(av.y,bv.w,acc[1][3]);
            acc[2][0] = fmaf(av.z,bv.x,acc[2][0]); acc[2][1] = fmaf(av.z,bv.y,acc[2][1]);
            acc[2][2] = fmaf(av.z,bv.z,acc[2][2]); acc[2][3] = fmaf(av.z,bv.w,acc[2][3]);
            acc[3][0] = fmaf(av.w,bv.x,acc[3][0]); acc[3][1] = fmaf(av.w,bv.y,acc[3][1]);
            acc[3][2] = fmaf(av.w,bv.z,acc[3][2]); acc[3][3] = fmaf(av.w,bv.w,acc[3][3]);
        }
        __syncthreads();
        cur ^= 1;
    }
    #undef CPREF
    #pragma unroll
    for (int i = 0; i < 4; i++){
        int w = (wh<<5) + (ty<<2) + i;
        #pragma unroll
        for (int j = 0; j < 4; j++){
            int co = (tx<<2)+j;
            float v = acc[i][j] + bias[co];
            if (MODE == 0)
                g_c1[(((b<<6)+co)<<12) + (hh<<6) + w] = fmaxf(v, 0.f);
            else
                g_t[(((b<<12) + (hh<<6) + w)<<6) + co] = v;
        }
    }
}

// ------------------------- 128-thread SGEMM 64x64, 8x4 microtile, fused LN, resident A+B, 1 barrier -------------------------
template<int HASB>
__global__ void __launch_bounds__(128) gemmln_kernel(const float* __restrict__ A,
                                                     const float* __restrict__ W,
                                                     const float* __restrict__ lnw,
                                                     const float* __restrict__ lnb,
                                                     const float* __restrict__ bias,
                                                     float* __restrict__ out, int N){
    __shared__ float As[64][68];                      // [k][m], LN'ed
    __shared__ float Bs[64][68];                      // [k][n], resident
    int t = threadIdx.x, tx = t & 15, ty = t >> 4;    // ty 0..7 (m-groups of 8)
    int m0 = blockIdx.x << 6, n0 = blockIdx.y << 6;
    // ---- B fill: all 64 k, transposed ----
    {
        int n = t & 63, kh = t >> 6;                  // kh 0/1 -> k 32-half
        const float* wp = W + (size_t)(n0+n)*64 + kh*32;
        #pragma unroll
        for (int j = 0; j < 32; j += 4){
            float4 f = *(const float4*)(wp + j);
            Bs[kh*32+j+0][n] = f.x; Bs[kh*32+j+1][n] = f.y;
            Bs[kh*32+j+2][n] = f.z; Bs[kh*32+j+3][n] = f.w;
        }
    }
    // ---- LN prologue: 64 rows, 2 threads/row (32 cols each) ----
    {
        int row = t >> 1, q = t & 1;
        float v[32];
        const float* ap = A + (size_t)(m0+row)*64 + q*32;
        #pragma unroll
        for (int j = 0; j < 32; j += 4){
            float4 f = *(const float4*)(ap + j);
            v[j] = f.x; v[j+1] = f.y; v[j+2] = f.z; v[j+3] = f.w;
        }
        float s = 0.f;
        #pragma unroll
        for (int j = 0; j < 32; j++) s += v[j];
        s += __shfl_xor_sync(0xffffffffu, s, 1);
        float mean = s * (1.f/64.f);
        float var = 0.f;
        #pragma unroll
        for (int j = 0; j < 32; j++){ float d = v[j]-mean; var += d*d; }
        var += __shfl_xor_sync(0xffffffffu, var, 1);
        float inv = rsqrtf(var * (1.f/64.f) + 1e-5f);
        #pragma unroll
        for (int j = 0; j < 32; j++){
            int col = q*32 + j;
            As[col][row] = (v[j]-mean)*inv*lnw[col] + lnb[col];
        }
    }
    __syncthreads();
    float acc[8][4] = {};
    #pragma unroll 8
    for (int k = 0; k < 64; k++){
        float a[8];
        *(float4*)&a[0] = *(const float4*)&As[k][ty*8];
        *(float4*)&a[4] = *(const float4*)&As[k][ty*8 + 4];
        float4 bv = *(const float4*)&Bs[k][tx<<2];
        #pragma unroll
        for (int i = 0; i < 8; i++){
            acc[i][0] = fmaf(a[i], bv.x, acc[i][0]);
            acc[i][1] = fmaf(a[i], bv.y, acc[i][1]);
            acc[i][2] = fmaf(a[i], bv.z, acc[i][2]);
            acc[i][3] = fmaf(a[i], bv.w, acc[i][3]);
        }
    }
    #pragma unroll
    for (int i = 0; i < 8; i++){
        int m = m0 + ty*8 + i;
        #pragma unroll
        for (int j = 0; j < 4; j++){
            int n = n0 + (tx<<2) + j;
            float v = acc[i][j];
            if (HASB) v += bias[n];
            out[(size_t)m*N + n] = v;
        }
    }
}

// ------------------------- 128-thread SGEMM 64x64, 8x4 microtile, K=128, EPI_SCAN -------------------------
__global__ void __launch_bounds__(128) gemmscan_kernel(const float* __restrict__ A,
                                                       const float* __restrict__ W,
                                                       const float* __restrict__ bias){
    __shared__ float As[2][16][68];
    __shared__ __align__(16) float Bs[2][16*68];
    int t = threadIdx.x, tx = t & 15, ty = t >> 4;
    int m0 = blockIdx.x << 6, n0 = blockIdx.y << 6;
    float acc[8][4] = {};
    int am = t & 63, ah = t >> 6;                     // A fill: row am, k-sub ah*8
    int bn = t & 63, bh = t >> 6;                     // B fill: row bn, k-sub bh*8
    float4 ap0 = *(const float4*)(A + (size_t)(m0+am)*128 + ah*8);
    float4 ap1 = *(const float4*)(A + (size_t)(m0+am)*128 + ah*8 + 4);
    float4 bp0 = *(const float4*)(W + (size_t)(n0+bn)*128 + bh*8);
    float4 bp1 = *(const float4*)(W + (size_t)(n0+bn)*128 + bh*8 + 4);
    int cur = 0;
    for (int kt = 0; kt < 128; kt += 16){
        float aa[8], bb[8];
        *(float4*)&aa[0] = ap0; *(float4*)&aa[4] = ap1;
        *(float4*)&bb[0] = bp0; *(float4*)&bb[4] = bp1;
        #pragma unroll
        for (int j = 0; j < 8; j++){
            As[cur][ah*8 + j][am] = aa[j];
            Bs[cur][(bh*8 + j)*68 + bn] = bb[j];
        }
        __syncthreads();
        if (kt + 16 < 128){
            ap0 = *(const float4*)(A + (size_t)(m0+am)*128 + kt + 16 + ah*8);
            ap1 = *(const float4*)(A + (size_t)(m0+am)*128 + kt + 16 + ah*8 + 4);
            bp0 = *(const float4*)(W + (size_t)(n0+bn)*128 + kt + 16 + bh*8);
            bp1 = *(const float4*)(W + (size_t)(n0+bn)*128 + kt + 16 + bh*8 + 4);
        }
        #pragma unroll
        for (int k = 0; k < 16; k++){
            float a[8];
            *(float4*)&a[0] = *(const float4*)&As[cur][k][ty*8];
            *(float4*)&a[4] = *(const float4*)&As[cur][k][ty*8 + 4];
            float4 bv = *(const float4*)&Bs[cur][k*68 + (tx<<2)];
            #pragma unroll
            for (int i = 0; i < 8; i++){
                acc[i][0] = fmaf(a[i], bv.x, acc[i][0]);
                acc[i][1] = fmaf(a[i], bv.y, acc[i][1]);
                acc[i][2] = fmaf(a[i], bv.z, acc[i][2]);
                acc[i][3] = fmaf(a[i], bv.w, acc[i][3]);
            }
        }
        __syncthreads();
        cur ^= 1;
    }
    #pragma unroll
    for (int i = 0; i < 8; i++){
        int m = m0 + ty*8 + i;
        #pragma unroll
        for (int j = 0; j < 4; j++){
            int n = n0 + (tx<<2) + j;
            float v = acc[i][j];
            if (n < 64)       g_Brow[(size_t)m*64 + n] = v;
            else if (n < 128) g_Crow[(size_t)m*64 + n - 64] = v;
            else {
                float xv = v + bias[n - 128];
                float sp = fmaxf(xv, 0.f) + log1pf(expf(-fabsf(xv)));
                int b = m >> 12, tt = m & 4095, q = tt >> 2, r = tt & 3;
                g_d4[(((size_t)(b*1024+q)*128 + (n-128))<<2) + r] = sp;
            }
        }
    }
}

// ------------------------- SGEMM 32x64 tiles, 128 threads, 4x4 microtile (N=64 exact) -------------------------
#define EPI_ADD 2
#define EPI_FINAL 3
template<int EPI>
__global__ void __launch_bounds__(128) gemm32_kernel(const float* __restrict__ A,
                                                     const float* __restrict__ W,
                                                     const float* __restrict__ bias,
                                                     float* __restrict__ out, int K,
                                                     const float* __restrict__ xres,
                                                     const float* __restrict__ tres){
    __shared__ float As[2][16][36];                   // [buf][k][m(32)]
    __shared__ __align__(16) float Bs[2][16*68];
    __shared__ __align__(16) float St[64][36];        // staged [n][m] for FINAL
    int t = threadIdx.x, tx = t & 15, ty = t >> 4;    // ty 0..7
    int m0 = blockIdx.x << 5;
    float acc[4][4] = {};
    int am = t >> 2, akg = (t & 3) << 2;              // am 0..31
    int bn = t >> 2, bkg = (t & 3) << 2;              // rows bn, bn+32
    float4 apre = *(const float4*)(A + (size_t)(m0+am)*K + akg);
    float4 bpre0 = *(const float4*)(W + (size_t)bn*K + bkg);
    float4 bpre1 = *(const float4*)(W + (size_t)(bn+32)*K + bkg);
    int cur = 0;
    for (int kt = 0; kt < K; kt += 16){
        As[cur][akg+0][am] = apre.x; As[cur][akg+1][am] = apre.y;
        As[cur][akg+2][am] = apre.z; As[cur][akg+3][am] = apre.w;
        Bs[cur][(bkg+0)*68 + bn] = bpre0.x; Bs[cur][(bkg+1)*68 + bn] = bpre0.y;
        Bs[cur][(bkg+2)*68 + bn] = bpre0.z; Bs[cur][(bkg+3)*68 + bn] = bpre0.w;
        Bs[cur][(bkg+0)*68 + bn+32] = bpre1.x; Bs[cur][(bkg+1)*68 + bn+32] = bpre1.y;
        Bs[cur][(bkg+2)*68 + bn+32] = bpre1.z; Bs[cur][(bkg+3)*68 + bn+32] = bpre1.w;
        __syncthreads();
        if (kt + 16 < K){
            apre  = *(const float4*)(A + (size_t)(m0+am)*K + kt + 16 + akg);
            bpre0 = *(const float4*)(W + (size_t)bn*K + kt + 16 + bkg);
            bpre1 = *(const float4*)(W + (size_t)(bn+32)*K + kt + 16 + bkg);
        }
        #pragma unroll
        for (int k = 0; k < 16; k++){
            float4 a4 = *(const float4*)&As[cur][k][ty<<2];
            float4 bv = *(const float4*)&Bs[cur][k*68 + (tx<<2)];
            acc[0][0] = fmaf(a4.x,bv.x,acc[0][0]); acc[0][1] = fmaf(a4.x,bv.y,acc[0][1]);
            acc[0][2] = fmaf(a4.x,bv.z,acc[0][2]); acc[0][3] = fmaf(a4.x,bv.w,acc[0][3]);
            acc[1][0] = fmaf(a4.y,bv.x,acc[1][0]); acc[1][1] = fmaf(a4.y,bv.y,acc[1][1]);
            acc[1][2] = fmaf(a4.y,bv.z,acc[1][2]); acc[1][3] = fmaf(a4.y,bv.w,acc[1][3]);
            acc[2][0] = fmaf(a4.z,bv.x,acc[2][0]); acc[2][1] = fmaf(a4.z,bv.y,acc[2][1]);
            acc[2][2] = fmaf(a4.z,bv.z,acc[2][2]); acc[2][3] = fmaf(a4.z,bv.w,acc[2][3]);
            acc[3][0] = fmaf(a4.w,bv.x,acc[3][0]); acc[3][1] = fmaf(a4.w,bv.y,acc[3][1]);
            acc[3][2] = fmaf(a4.w,bv.z,acc[3][2]); acc[3][3] = fmaf(a4.w,bv.w,acc[3][3]);
        }
        __syncthreads();
        cur ^= 1;
    }
    if (EPI == EPI_ADD){
        #pragma unroll
        for (int i = 0; i < 4; i++){
            int m = m0 + (ty<<2) + i;
            #pragma unroll
            for (int j = 0; j < 4; j++){
                int n = (tx<<2) + j;
                out[(size_t)m*64 + n] += acc[i][j];
            }
        }
    } else {
        // FINAL: stage v + bias + tres transposed, then coalesced NCHW write adding x
        int b = m0 >> 12, l0 = m0 & 4095;
        #pragma unroll
        for (int i = 0; i < 4; i++){
            int m = m0 + (ty<<2) + i;
            float4 tr = *(const float4*)(tres + (size_t)m*64 + (tx<<2));
            St[(tx<<2)+0][(ty<<2)+i] = acc[i][0] + tr.x + bias[(tx<<2)+0];
            St[(tx<<2)+1][(ty<<2)+i] = acc[i][1] + tr.y + bias[(tx<<2)+1];
            St[(tx<<2)+2][(ty<<2)+i] = acc[i][2] + tr.z + bias[(tx<<2)+2];
            St[(tx<<2)+3][(ty<<2)+i] = acc[i][3] + tr.w + bias[(tx<<2)+3];
        }
        __syncthreads();
        #pragma unroll
        for (int r = 0; r < 4; r++){
            int q = t + r*128;
            int n = q >> 3, cch = q & 7;
            float4 s = *(const float4*)&St[n][cch<<2];
            size_t oi = (((size_t)(b*64 + n)) << 12) + l0 + (cch<<2);
            float4 xr = *(const float4*)(xres + oi);
            s.x += xr.x; s.y += xr.y; s.z += xr.z; s.w += xr.w;
            *(float4*)(out + oi) = s;
        }
    }
}

// ------------------------- causal dwconv1d + silu -------------------------
__global__ void conv1d_kernel(const float* __restrict__ cw, const float* __restrict__ cb){
    int idx = blockIdx.x*256 + threadIdx.x;           // M*128
    int d = idx & 127, m = idx >> 7;
    int b = m >> 12, tt = m & 4095;
    float acc = cb[d];
    #pragma unroll
    for (int k = 0; k < 4; k++){
        int t2 = tt - 3 + k;
        if (t2 >= 0) acc = fmaf(cw[d*4 + k], g_xz[(size_t)((b<<12)+t2)*256 + d], acc);
    }
    float s = acc / (1.f + expf(-acc));
    g_xc[(size_t)m*128 + d] = s;
    int q = tt >> 2, r = tt & 3;
    g_xc4[(((size_t)(b*1024+q)*128 + d)<<2) + r] = s;
}

// ------------------------- scan pass 1a: per-chunk summaries (S, P) -------------------------
__global__ void __launch_bounds__(256) scan1_kernel(const float* __restrict__ Alog){
    __shared__ float Bsh[64][64];
    int dg = blockIdx.x, c = blockIdx.y, b = blockIdx.z;
    int tid = threadIdx.x, w = tid >> 5, lane = tid & 31;
    int d = dg*8 + w, n0 = lane, n1 = lane + 32;
    float A0 = -__expf(Alog[d*64 + n0]);
    float A1 = -__expf(Alog[d*64 + n1]);
    float h0 = 0.f, h1 = 0.f, sd = 0.f;
    const float4* dp4 = (const float4*)g_d4  + (size_t)b*1024*128 + d;
    const float4* up4 = (const float4*)g_xc4 + (size_t)b*1024*128 + d;
    for (int s = 0; s < 4; s++){
        int m0 = b*4096 + c*256 + s*64;
        __syncthreads();
        #pragma unroll
        for (int rep = 0; rep < 4; rep++){
            int i = rep*256 + tid; int row = i >> 4, v = i & 15;
            *(float4*)&Bsh[row][v*4] = *(const float4*)(g_Brow + (size_t)(m0+row)*64 + v*4);
        }
        __syncthreads();
        int qb = (c*256 + s*64) >> 2;
        float4 dq = dp4[(size_t)qb*128], uq = up4[(size_t)qb*128];
        for (int qi = 0; qi < 16; qi++){
            float4 dc = dq, uc = uq;
            if (qi < 15){ dq = dp4[(size_t)(qb+qi+1)*128]; uq = up4[(size_t)(qb+qi+1)*128]; }
            float dv[4], uv[4];
            *(float4*)dv = dc; *(float4*)uv = uc;
            #pragma unroll
            for (int j = 0; j < 4; j++){
                int row = qi*4 + j;
                float du = dv[j]*uv[j];
                h0 = fmaf(h0, __expf(dv[j]*A0), du*Bsh[row][n0]);
                h1 = fmaf(h1, __expf(dv[j]*A1), du*Bsh[row][n1]);
                sd += dv[j];
            }
        }
    }
    size_t base = ((size_t)((b*NCH + c)*128 + d))*64;
    g_S[base + n0] = h0;              g_S[base + n1] = h1;
    g_P[base + n0] = __expf(sd*A0);   g_P[base + n1] = __expf(sd*A1);
}

// ------------------------- scan pass 1b: combine chunk summaries -> h_init -------------------------
__global__ void scan2_kernel(){
    int wg = blockIdx.x*4 + (threadIdx.x >> 5);  // 0..255 = (b,d)
    int lane = threadIdx.x & 31;
    int b = wg >> 7, d = wg & 127;
    float h0 = 0.f, h1 = 0.f;
    for (int c = 0; c < NCH; c++){
        size_t base = ((size_t)((b*NCH + c)*128 + d))*64;
        g_Hi[base + lane]      = h0;
        g_Hi[base + 32 + lane] = h1;
        h0 = fmaf(g_P[base + lane],      h0, g_S[base + lane]);
        h1 = fmaf(g_P[base + 32 + lane], h1, g_S[base + 32 + lane]);
    }
}

// ------------------------- scan pass 2: full scan + batched 4-row reductions -------------------------
__global__ void __launch_bounds__(256) scan3_kernel(const float* __restrict__ Alog,
                                                    const float* __restrict__ Dp){
    __shared__ float Bsh[64][64];
    __shared__ float Csh[64][64];
    __shared__ float Zsh[64][8];
    int dg = blockIdx.x, c = blockIdx.y, b = blockIdx.z;
    int tid = threadIdx.x, w = tid >> 5, lane = tid & 31;
    int d = dg*8 + w, n0 = lane, n1 = lane + 32;
    float A0 = -__expf(Alog[d*64 + n0]);
    float A1 = -__expf(Alog[d*64 + n1]);
    float Dd = Dp[d];
    size_t hbase = ((size_t)((b*NCH + c)*128 + d))*64;
    float h0 = g_Hi[hbase + n0], h1 = g_Hi[hbase + n1];
    const float4* dp4 = (const float4*)g_d4  + (size_t)b*1024*128 + d;
    const float4* up4 = (const float4*)g_xc4 + (size_t)b*1024*128 + d;
    for (int s = 0; s < 4; s++){
        int m0 = b*4096 + c*256 + s*64;
        __syncthreads();
        #pragma unroll
        for (int rep = 0; rep < 4; rep++){
            int i = rep*256 + tid; int row = i >> 4, v = i & 15;
            *(float4*)&Bsh[row][v*4] = *(const float4*)(g_Brow + (size_t)(m0+row)*64 + v*4);
            *(float4*)&Csh[row][v*4] = *(const float4*)(g_Crow + (size_t)(m0+row)*64 + v*4);
        }
        if (tid < 128){
            int row = tid >> 1, hf = tid & 1;
            *(float4*)&Zsh[row][hf*4] =
                *(const float4*)(g_xz + (size_t)(m0+row)*256 + 128 + dg*8 + hf*4);
        }
        __syncthreads();
        int qb = (c*256 + s*64) >> 2;
        float4 dq = dp4[(size_t)qb*128], uq = up4[(size_t)qb*128];
        for (int qi = 0; qi < 16; qi++){
            float4 dc = dq, uc = uq;
            if (qi < 15){ dq = dp4[(size_t)(qb+qi+1)*128]; uq = up4[(size_t)(qb+qi+1)*128]; }
            float dv[4], uv[4], pr[4];
            *(float4*)dv = dc; *(float4*)uv = uc;
            #pragma unroll
            for (int j = 0; j < 4; j++){
                int row = qi*4 + j;
                float du = dv[j]*uv[j];
                h0 = fmaf(h0, __expf(dv[j]*A0), du*Bsh[row][n0]);
                h1 = fmaf(h1, __expf(dv[j]*A1), du*Bsh[row][n1]);
                pr[j] = fmaf(h0, Csh[row][n0], h1*Csh[row][n1]);
            }
            #pragma unroll
            for (int o = 16; o > 0; o >>= 1){
                pr[0] += __shfl_xor_sync(0xffffffffu, pr[0], o);
                pr[1] += __shfl_xor_sync(0xffffffffu, pr[1], o);
                pr[2] += __shfl_xor_sync(0xffffffffu, pr[2], o);
                pr[3] += __shfl_xor_sync(0xffffffffu, pr[3], o);
            }
            if (lane < 4){
                float pv  = (lane == 0) ? pr[0] : (lane == 1) ? pr[1] : (lane == 2) ? pr[2] : pr[3];
                float uvv = (lane == 0) ? uv[0] : (lane == 1) ? uv[1] : (lane == 2) ? uv[2] : uv[3];
                int row = qi*4 + lane;
                float z = Zsh[row][w];
                float sz = z / (1.f + __expf(-z));
                g_yg[(size_t)(m0+row)*128 + d] = (pv + uvv*Dd) * sz;
            }
        }
    }
}

// ------------------------- depthwise 3x3 conv + gelu, rolling 3-col window -------------------------
__global__ void __launch_bounds__(256) dwconv_kernel(const float* __restrict__ dww,
                                                     const float* __restrict__ dwb){
    int blk = blockIdx.x;                              // ((b*64 + y)*2 + xh) : 256 blocks
    int xh = blk & 1, rest = blk >> 1;
    int b = rest >> 6, y = rest & 63;
    int ch = threadIdx.x;                              // 256 channels
    float wgt[9];
    #pragma unroll
    for (int j = 0; j < 9; j++) wgt[j] = dww[ch*9 + j];
    float bb = dwb[ch];
    bool v0 = (y > 0), v2 = (y < 63);
    const float* r0 = g_h1 + (((size_t)(b<<12) + ((y-1)<<6)) << 8) + ch;
    const float* r1 = g_h1 + (((size_t)(b<<12) + ( y   <<6)) << 8) + ch;
    const float* r2 = g_h1 + (((size_t)(b<<12) + ((y+1)<<6)) << 8) + ch;
    float* outp = g_g + (((size_t)(b<<12) + (y<<6)) << 8) + ch;
    int x0 = xh << 5;
    float cp0, cp1, cp2, cc0, cc1, cc2;
    {
        int xm = x0 - 1;
        bool xv = (xm >= 0);
        cp0 = (xv && v0) ? r0[(size_t)xm << 8] : 0.f;
        cp1 =  xv        ? r1[(size_t)xm << 8] : 0.f;
        cp2 = (xv && v2) ? r2[(size_t)xm << 8] : 0.f;
        cc0 = v0 ? r0[(size_t)x0 << 8] : 0.f;
        cc1 =      r1[(size_t)x0 << 8];
        cc2 = v2 ? r2[(size_t)x0 << 8] : 0.f;
    }
    #pragma unroll 4
    for (int i = 0; i < 32; i++){
        int x = x0 + i;
        bool xv = (x + 1 < 64);
        float cn0 = (xv && v0) ? r0[(size_t)(x+1) << 8] : 0.f;
        float cn1 =  xv        ? r1[(size_t)(x+1) << 8] : 0.f;
        float cn2 = (xv && v2) ? r2[(size_t)(x+1) << 8] : 0.f;
        float acc = bb;
        acc = fmaf(wgt[0], cp0, acc); acc = fmaf(wgt[1], cc0, acc); acc = fmaf(wgt[2], cn0, acc);
        acc = fmaf(wgt[3], cp1, acc); acc = fmaf(wgt[4], cc1, acc); acc = fmaf(wgt[5], cn1, acc);
        acc = fmaf(wgt[6], cp2, acc); acc = fmaf(wgt[7], cc2, acc); acc = fmaf(wgt[8], cn2, acc);
        outp[(size_t)x << 8] = 0.5f*acc*(1.f + erff(acc*0.70710678118654752f));
        cp0 = cc0; cp1 = cc1; cp2 = cc2;
        cc0 = cn0; cc1 = cn1; cc2 = cn2;
    }
}

// ------------------------- host launch -------------------------
extern "C" void kernel_launch(void* const* d_in, const int* in_sizes, int n_in,
                              void* d_out, int out_size){
    const float* x        = (const float*)d_in[0];
    const float* conv1_w  = (const float*)d_in[1];
    const float* conv1_b  = (const float*)d_in[2];
    const float* conv2_w  = (const float*)d_in[3];
    const float* conv2_b  = (const float*)d_in[4];
    const float* ln1_w    = (const float*)d_in[5];
    const float* ln1_b    = (const float*)d_in[6];
    const float* ln2_w    = (const float*)d_in[7];
    const float* ln2_b    = (const float*)d_in[8];
    const float* in_proj  = (const float*)d_in[9];
    const float* c1d_w    = (const float*)d_in[10];
    const float* c1d_b    = (const float*)d_in[11];
    const float* xproj_w  = (const float*)d_in[12];
    const float* dtp_w    = (const float*)d_in[13];
    const float* dtp_b    = (const float*)d_in[14];
    const float* A_log    = (const float*)d_in[15];
    const float* D_param  = (const float*)d_in[16];
    const float* outp_w   = (const float*)d_in[17];
    const float* fc1_w    = (const float*)d_in[18];
    const float* fc1_b    = (const float*)d_in[19];
    const float* dw_w     = (const float*)d_in[20];
    const float* dw_b     = (const float*)d_in[21];
    const float* fc2_w    = (const float*)d_in[22];
    const float* fc2_b    = (const float*)d_in[23];
    float* out = (float*)d_out;

    float *p_t, *p_xz, *p_xc, *p_yg, *p_h1, *p_g, *p_c1, *p_w1t, *p_w2t, *p_wcat;
    cudaGetSymbolAddress((void**)&p_t,    g_t);
    cudaGetSymbolAddress((void**)&p_xz,   g_xz);
    cudaGetSymbolAddress((void**)&p_xc,   g_xc);
    cudaGetSymbolAddress((void**)&p_yg,   g_yg);
    cudaGetSymbolAddress((void**)&p_h1,   g_h1);
    cudaGetSymbolAddress((void**)&p_g,    g_g);
    cudaGetSymbolAddress((void**)&p_c1,   g_c1);
    cudaGetSymbolAddress((void**)&p_w1t,  g_w1t);
    cudaGetSymbolAddress((void**)&p_w2t,  g_w2t);
    cudaGetSymbolAddress((void**)&p_wcat, g_wcat);

    prep_kernel<<<(KCONV*CC + 255)/256, 256>>>(conv1_w, conv2_w, xproj_w, dtp_w);

    conv3_kernel<0><<<BB*HH*2, 128>>>(x,    p_w1t, conv1_b);
    conv3_kernel<1><<<BB*HH*2, 128>>>(p_c1, p_w2t, conv2_b);

    // mamba branch (LN fused into in_proj GEMM, 8x4 microtile, 1 barrier)
    gemmln_kernel<0><<<dim3(MM/64, 4), 128>>>(p_t, in_proj, ln1_w, ln1_b, nullptr,
                                              p_xz, 256);
    conv1d_kernel<<<MM*DIN/256, 256>>>(c1d_w, c1d_b);
    gemmscan_kernel<<<dim3(MM/64, 4), 128>>>(p_xc, p_wcat, dtp_b);

    scan1_kernel<<<dim3(16, NCH, BB), 256>>>(A_log);
    scan2_kernel<<<64, 128>>>();
    scan3_kernel<<<dim3(16, NCH, BB), 256>>>(A_log, D_param);

    gemm32_kernel<EPI_ADD><<<MM/32, 128>>>(p_yg, outp_w, nullptr, p_t, 128,
                                           nullptr, nullptr);

    // FFN branch (LN fused into fc1 GEMM)
    gemmln_kernel<1><<<dim3(MM/64, 4), 128>>>(p_t, fc1_w, ln2_w, ln2_b, fc1_b,
                                              p_h1, 256);
    dwconv_kernel<<<BB*HH*2, 256>>>(dw_w, dw_b);
    gemm32_kernel<EPI_FINAL><<<MM/32, 128>>>(p_g, fc2_w, fc2_b, out, 256,
                                             x, p_t);
}

// round 15
// speedup vs baseline: 1.0250x; 1.0250x over previous
#include <cuda_runtime.h>
#include <math.h>

#define BB 2
#define CC 64
#define HH 64
#define WW 64
#define LL 4096
#define MM (BB*LL)          // 8192 tokens
#define DIN 128             // D_INNER
#define DST 64              // D_STATE
#define DTR 4               // DT_RANK
#define HID 256             // HIDDEN
#define KCONV 576           // 64*9
#define NCH 16              // chunks

// ------------------------- scratch buffers (device globals) -------------------------
__device__ float g_c1   [BB*CC*HH*WW];      // conv1 out NCHW
__device__ float g_t    [MM*CC];            // tokens (B,L,64), residual accumulator
__device__ float g_xz   [MM*2*DIN];         // in_proj out: [:,:128]=xin, [:,128:]=z
__device__ float g_xc   [MM*DIN];           // conv1d+silu out (row major)
__device__ float g_xc4  [MM*DIN];           // same, blocked (B, L/4, 128, 4)
__device__ float g_Brow [MM*DST];           // B row-major (m,64)
__device__ float g_Crow [MM*DST];           // C row-major (m,64)
__device__ float g_d4   [MM*DIN];           // delta blocked (B, L/4, 128, 4)
__device__ float g_P    [BB*NCH*DIN*DST];   // per-chunk decay
__device__ float g_S    [BB*NCH*DIN*DST];   // per-chunk local final state
__device__ float g_Hi   [BB*NCH*DIN*DST];   // per-chunk initial state
__device__ float g_yg   [MM*DIN];           // gated y
__device__ float g_h1   [MM*HID];           // fc1 out
__device__ float g_g    [MM*HID];           // dwconv+gelu out
__device__ float g_w1t  [KCONV*CC];         // conv1 weight reordered [(seg,ci)][co]
__device__ float g_w2t  [KCONV*CC];         // conv2 weight reordered
__device__ float g_wcat [256*DIN];          // [B rows | C rows | dtw@xprojw_dt] (256 x 128)

// ------------------------- merged weight prep -------------------------
__global__ void prep_kernel(const float* __restrict__ w1, const float* __restrict__ w2,
                            const float* __restrict__ xprojw, const float* __restrict__ dtw){
    int i = blockIdx.x*256 + threadIdx.x;
    if (i < KCONV*CC){
        int k = i >> 6, co = i & 63;
        int seg = k >> 6, ci = k & 63;
        int src = co*KCONV + ci*9 + seg;
        g_w1t[i] = w1[src];
        g_w2t[i] = w2[src];
    }
    if (i < 256*DIN){
        int n = i >> 7, k = i & 127;
        float v;
        if (n < 64)       v = xprojw[(4 + n)*DIN + k];
        else if (n < 128) v = xprojw[(68 + n - 64)*DIN + k];
        else {
            int dd = n - 128;
            v = dtw[dd*4+0]*xprojw[0*DIN + k] + dtw[dd*4+1]*xprojw[1*DIN + k]
              + dtw[dd*4+2]*xprojw[2*DIN + k] + dtw[dd*4+3]*xprojw[3*DIN + k];
        }
        g_wcat[i] = v;
    }
}

// ------------------------- implicit-GEMM 3x3 conv, 128-thread 32x64 tiles, double-buffered -------------------------
template<int MODE>
__global__ void __launch_bounds__(128) conv3_kernel(const float* __restrict__ in,
                                                    const float* __restrict__ wt,
                                                    const float* __restrict__ bias){
    __shared__ float As[2][32][36];                   // [buf][k(ci)][m(w)]
    __shared__ __align__(16) float Bs[2][32*68];
    int blk = blockIdx.x;
    int b = blk >> 7, rest = blk & 127;
    int hh = rest >> 1, wh = rest & 1;                // w half
    int t = threadIdx.x, tx = t & 15, ty = t >> 4;    // ty 0..7 (w quads), tx 0..15 (co quads)
    float acc[4][4] = {};
    int aw = t & 31, ci0 = t >> 5;                    // A fill: w=aw, ci = ci0 + 4*jj (jj 0..7)
    int bk = t >> 4, bcg = (t & 15) << 2;             // B fill: rows bk + 8*r (r 0..3)
    float ar[8]; float4 br[4];

    #define CPREF(cc) { \
        int seg = (cc) >> 1, kh = (cc) & 1; \
        int ky = seg / 3, kx = seg - ky*3; \
        int y = hh + ky - 1, x = (wh<<5) + aw + kx - 1; \
        bool ok = (y >= 0) && (y < 64) && (x >= 0) && (x < 64); \
        const float* src = in + (((size_t)b << 18) + ((size_t)(kh*32 + ci0) << 12) + (y << 6) + x); \
        _Pragma("unroll") \
        for (int jj = 0; jj < 8; jj++) ar[jj] = ok ? src[(size_t)(jj*4) << 12] : 0.f; \
        const float* wp = wt + (size_t)(seg*64 + kh*32 + bk)*64 + bcg; \
        _Pragma("unroll") \
        for (int r = 0; r < 4; r++) br[r] = *(const float4*)(wp + (size_t)(r*8)*64); }

    CPREF(0);
    int cur = 0;
    #pragma unroll 1
    for (int cc = 0; cc < 18; cc++){
        #pragma unroll
        for (int jj = 0; jj < 8; jj++) As[cur][ci0 + jj*4][aw] = ar[jj];
        #pragma unroll
        for (int r = 0; r < 4; r++) *(float4*)&Bs[cur][(bk + r*8)*68 + bcg] = br[r];
        __syncthreads();
        if (cc < 17) CPREF(cc+1);
        #pragma unroll
        for (int k = 0; k < 32; k++){
            float4 av = *(const float4*)&As[cur][k][ty<<2];
            float4 bv = *(const float4*)&Bs[cur][k*68 + (tx<<2)];
            acc[0][0] = fmaf(av.x,bv.x,acc[0][0]); acc[0][1] = fmaf(av.x,bv.y,acc[0][1]);
            acc[0][2] = fmaf(av.x,bv.z,acc[0][2]); acc[0][3] = fmaf(av.x,bv.w,acc[0][3]);
            acc[1][0] = fmaf(av.y,bv.x,acc[1][0]); acc[1][1] = fmaf(av.y,bv.y,acc[1][1]);
            acc[1][2] = fmaf(av.y,bv.z,acc[1][2]); acc[1][3] = fmaf(av.y,bv.w,acc[1][3]);
            acc[2][0] = fmaf(av.z,bv.x,acc[2][0]); acc[2][1] = fmaf(av.z,bv.y,acc[2][1]);
            acc[2][2] = fmaf(av.z,bv.z,acc[2][2]); acc[2][3] = fmaf(av.z,bv.w,acc[2][3]);
            acc[3][0] = fmaf(av.w,bv.x,acc[3][0]); acc[3][1] = fmaf(av.w,bv.y,acc[3][1]);
            acc[3][2] = fmaf(av.w,bv.z,acc[3][2]); acc[3][3] = fmaf(av.w,bv.w,acc[3][3]);
        }
        __syncthreads();
        cur ^= 1;
    }
    #undef CPREF
    #pragma unroll
    for (int i = 0; i < 4; i++){
        int w = (wh<<5) + (ty<<2) + i;
        #pragma unroll
        for (int j = 0; j < 4; j++){
            int co = (tx<<2)+j;
            float v = acc[i][j] + bias[co];
            if (MODE == 0)
                g_c1[(((b<<6)+co)<<12) + (hh<<6) + w] = fmaxf(v, 0.f);
            else
                g_t[(((b<<12) + (hh<<6) + w)<<6) + co] = v;
        }
    }
}

// ------------------------- 128-thread SGEMM 64x64, 8x4 microtile, fused LN on A (K=64) -------------------------
template<int HASB>
__global__ void __launch_bounds__(128) gemmln_kernel(const float* __restrict__ A,
                                                     const float* __restrict__ W,
                                                     const float* __restrict__ lnw,
                                                     const float* __restrict__ lnb,
                                                     const float* __restrict__ bias,
                                                     float* __restrict__ out, int N){
    __shared__ float As[64][68];                      // [k][m], LN'ed, resident
    __shared__ __align__(16) float Bs[2][16*68];
    int t = threadIdx.x, tx = t & 15, ty = t >> 4;    // ty 0..7 (m-groups of 8)
    int m0 = blockIdx.x << 6, n0 = blockIdx.y << 6;
    int bn = t & 63, bh = t >> 6;                     // B fill: row bn, k-sub bh*8
    float4 bp0 = *(const float4*)(W + (size_t)(n0+bn)*64 + bh*8);
    float4 bp1 = *(const float4*)(W + (size_t)(n0+bn)*64 + bh*8 + 4);
    // ---- LN prologue: 64 rows, 2 threads/row (32 cols each) ----
    {
        int row = t >> 1, q = t & 1;
        float v[32];
        const float* ap = A + (size_t)(m0+row)*64 + q*32;
        #pragma unroll
        for (int j = 0; j < 32; j += 4){
            float4 f = *(const float4*)(ap + j);
            v[j] = f.x; v[j+1] = f.y; v[j+2] = f.z; v[j+3] = f.w;
        }
        float s = 0.f;
        #pragma unroll
        for (int j = 0; j < 32; j++) s += v[j];
        s += __shfl_xor_sync(0xffffffffu, s, 1);
        float mean = s * (1.f/64.f);
        float var = 0.f;
        #pragma unroll
        for (int j = 0; j < 32; j++){ float d = v[j]-mean; var += d*d; }
        var += __shfl_xor_sync(0xffffffffu, var, 1);
        float inv = rsqrtf(var * (1.f/64.f) + 1e-5f);
        #pragma unroll
        for (int j = 0; j < 32; j++){
            int col = q*32 + j;
            As[col][row] = (v[j]-mean)*inv*lnw[col] + lnb[col];
        }
    }
    float acc[8][4] = {};
    int cur = 0;
    for (int kt = 0; kt < 64; kt += 16){
        float bb[8];
        *(float4*)&bb[0] = bp0; *(float4*)&bb[4] = bp1;
        #pragma unroll
        for (int j = 0; j < 8; j++) Bs[cur][(bh*8 + j)*68 + bn] = bb[j];
        __syncthreads();
        if (kt + 16 < 64){
            bp0 = *(const float4*)(W + (size_t)(n0+bn)*64 + kt + 16 + bh*8);
            bp1 = *(const float4*)(W + (size_t)(n0+bn)*64 + kt + 16 + bh*8 + 4);
        }
        #pragma unroll
        for (int k = 0; k < 16; k++){
            float a[8];
            *(float4*)&a[0] = *(const float4*)&As[kt+k][ty*8];
            *(float4*)&a[4] = *(const float4*)&As[kt+k][ty*8 + 4];
            float4 bv = *(const float4*)&Bs[cur][k*68 + (tx<<2)];
            #pragma unroll
            for (int i = 0; i < 8; i++){
                acc[i][0] = fmaf(a[i], bv.x, acc[i][0]);
                acc[i][1] = fmaf(a[i], bv.y, acc[i][1]);
                acc[i][2] = fmaf(a[i], bv.z, acc[i][2]);
                acc[i][3] = fmaf(a[i], bv.w, acc[i][3]);
            }
        }
        __syncthreads();
        cur ^= 1;
    }
    float4 bsv = make_float4(0.f,0.f,0.f,0.f);
    if (HASB) bsv = *(const float4*)(bias + n0 + (tx<<2));
    #pragma unroll
    for (int i = 0; i < 8; i++){
        int m = m0 + ty*8 + i;
        float4 o;
        o.x = acc[i][0] + bsv.x; o.y = acc[i][1] + bsv.y;
        o.z = acc[i][2] + bsv.z; o.w = acc[i][3] + bsv.w;
        *(float4*)(out + (size_t)m*N + n0 + (tx<<2)) = o;
    }
}

// ------------------------- 128-thread SGEMM 64x64, 8x4 microtile, K=128, EPI_SCAN -------------------------
__global__ void __launch_bounds__(128) gemmscan_kernel(const float* __restrict__ A,
                                                       const float* __restrict__ W,
                                                       const float* __restrict__ bias){
    __shared__ float As[2][16][68];
    __shared__ __align__(16) float Bs[2][16*68];
    int t = threadIdx.x, tx = t & 15, ty = t >> 4;
    int m0 = blockIdx.x << 6, n0 = blockIdx.y << 6;
    float acc[8][4] = {};
    int am = t & 63, ah = t >> 6;                     // A fill: row am, k-sub ah*8
    int bn = t & 63, bh = t >> 6;                     // B fill: row bn, k-sub bh*8
    float4 ap0 = *(const float4*)(A + (size_t)(m0+am)*128 + ah*8);
    float4 ap1 = *(const float4*)(A + (size_t)(m0+am)*128 + ah*8 + 4);
    float4 bp0 = *(const float4*)(W + (size_t)(n0+bn)*128 + bh*8);
    float4 bp1 = *(const float4*)(W + (size_t)(n0+bn)*128 + bh*8 + 4);
    int cur = 0;
    for (int kt = 0; kt < 128; kt += 16){
        float aa[8], bb[8];
        *(float4*)&aa[0] = ap0; *(float4*)&aa[4] = ap1;
        *(float4*)&bb[0] = bp0; *(float4*)&bb[4] = bp1;
        #pragma unroll
        for (int j = 0; j < 8; j++){
            As[cur][ah*8 + j][am] = aa[j];
            Bs[cur][(bh*8 + j)*68 + bn] = bb[j];
        }
        __syncthreads();
        if (kt + 16 < 128){
            ap0 = *(const float4*)(A + (size_t)(m0+am)*128 + kt + 16 + ah*8);
            ap1 = *(const float4*)(A + (size_t)(m0+am)*128 + kt + 16 + ah*8 + 4);
            bp0 = *(const float4*)(W + (size_t)(n0+bn)*128 + kt + 16 + bh*8);
            bp1 = *(const float4*)(W + (size_t)(n0+bn)*128 + kt + 16 + bh*8 + 4);
        }
        #pragma unroll
        for (int k = 0; k < 16; k++){
            float a[8];
            *(float4*)&a[0] = *(const float4*)&As[cur][k][ty*8];
            *(float4*)&a[4] = *(const float4*)&As[cur][k][ty*8 + 4];
            float4 bv = *(const float4*)&Bs[cur][k*68 + (tx<<2)];
            #pragma unroll
            for (int i = 0; i < 8; i++){
                acc[i][0] = fmaf(a[i], bv.x, acc[i][0]);
                acc[i][1] = fmaf(a[i], bv.y, acc[i][1]);
                acc[i][2] = fmaf(a[i], bv.z, acc[i][2]);
                acc[i][3] = fmaf(a[i], bv.w, acc[i][3]);
            }
        }
        __syncthreads();
        cur ^= 1;
    }
    // each blockIdx.y maps to one region: 0 -> Brow, 1 -> Crow, 2/3 -> delta
    if (n0 == 0){
        #pragma unroll
        for (int i = 0; i < 8; i++){
            int m = m0 + ty*8 + i;
            *(float4*)(g_Brow + (size_t)m*64 + (tx<<2)) =
                make_float4(acc[i][0], acc[i][1], acc[i][2], acc[i][3]);
        }
    } else if (n0 == 64){
        #pragma unroll
        for (int i = 0; i < 8; i++){
            int m = m0 + ty*8 + i;
            *(float4*)(g_Crow + (size_t)m*64 + (tx<<2)) =
                make_float4(acc[i][0], acc[i][1], acc[i][2], acc[i][3]);
        }
    } else {
        #pragma unroll
        for (int i = 0; i < 8; i++){
            int m = m0 + ty*8 + i;
            int b = m >> 12, tt = m & 4095, q = tt >> 2, r = tt & 3;
            #pragma unroll
            for (int j = 0; j < 4; j++){
                int dd = n0 - 128 + (tx<<2) + j;
                float xv = acc[i][j] + bias[dd];
                float sp = fmaxf(xv, 0.f) + log1pf(expf(-fabsf(xv)));
                g_d4[(((size_t)(b*1024+q)*128 + dd)<<2) + r] = sp;
            }
        }
    }
}

// ------------------------- SGEMM 32x64 tiles, 128 threads, 4x4 microtile (N=64 exact) -------------------------
#define EPI_ADD 2
#define EPI_FINAL 3
template<int EPI>
__global__ void __launch_bounds__(128) gemm32_kernel(const float* __restrict__ A,
                                                     const float* __restrict__ W,
                                                     const float* __restrict__ bias,
                                                     float* __restrict__ out, int K,
                                                     const float* __restrict__ xres,
                                                     const float* __restrict__ tres){
    __shared__ float As[2][16][36];                   // [buf][k][m(32)]
    __shared__ __align__(16) float Bs[2][16*68];
    __shared__ __align__(16) float St[64][36];        // staged [n][m] for FINAL
    int t = threadIdx.x, tx = t & 15, ty = t >> 4;    // ty 0..7
    int m0 = blockIdx.x << 5;
    float acc[4][4] = {};
    int am = t >> 2, akg = (t & 3) << 2;              // am 0..31
    int bn = t >> 2, bkg = (t & 3) << 2;              // rows bn, bn+32
    float4 apre = *(const float4*)(A + (size_t)(m0+am)*K + akg);
    float4 bpre0 = *(const float4*)(W + (size_t)bn*K + bkg);
    float4 bpre1 = *(const float4*)(W + (size_t)(bn+32)*K + bkg);
    int cur = 0;
    for (int kt = 0; kt < K; kt += 16){
        As[cur][akg+0][am] = apre.x; As[cur][akg+1][am] = apre.y;
        As[cur][akg+2][am] = apre.z; As[cur][akg+3][am] = apre.w;
        Bs[cur][(bkg+0)*68 + bn] = bpre0.x; Bs[cur][(bkg+1)*68 + bn] = bpre0.y;
        Bs[cur][(bkg+2)*68 + bn] = bpre0.z; Bs[cur][(bkg+3)*68 + bn] = bpre0.w;
        Bs[cur][(bkg+0)*68 + bn+32] = bpre1.x; Bs[cur][(bkg+1)*68 + bn+32] = bpre1.y;
        Bs[cur][(bkg+2)*68 + bn+32] = bpre1.z; Bs[cur][(bkg+3)*68 + bn+32] = bpre1.w;
        __syncthreads();
        if (kt + 16 < K){
            apre  = *(const float4*)(A + (size_t)(m0+am)*K + kt + 16 + akg);
            bpre0 = *(const float4*)(W + (size_t)bn*K + kt + 16 + bkg);
            bpre1 = *(const float4*)(W + (size_t)(bn+32)*K + kt + 16 + bkg);
        }
        #pragma unroll
        for (int k = 0; k < 16; k++){
            float4 a4 = *(const float4*)&As[cur][k][ty<<2];
            float4 bv = *(const float4*)&Bs[cur][k*68 + (tx<<2)];
            acc[0][0] = fmaf(a4.x,bv.x,acc[0][0]); acc[0][1] = fmaf(a4.x,bv.y,acc[0][1]);
            acc[0][2] = fmaf(a4.x,bv.z,acc[0][2]); acc[0][3] = fmaf(a4.x,bv.w,acc[0][3]);
            acc[1][0] = fmaf(a4.y,bv.x,acc[1][0]); acc[1][1] = fmaf(a4.y,bv.y,acc[1][1]);
            acc[1][2] = fmaf(a4.y,bv.z,acc[1][2]); acc[1][3] = fmaf(a4.y,bv.w,acc[1][3]);
            acc[2][0] = fmaf(a4.z,bv.x,acc[2][0]); acc[2][1] = fmaf(a4.z,bv.y,acc[2][1]);
            acc[2][2] = fmaf(a4.z,bv.z,acc[2][2]); acc[2][3] = fmaf(a4.z,bv.w,acc[2][3]);
            acc[3][0] = fmaf(a4.w,bv.x,acc[3][0]); acc[3][1] = fmaf(a4.w,bv.y,acc[3][1]);
            acc[3][2] = fmaf(a4.w,bv.z,acc[3][2]); acc[3][3] = fmaf(a4.w,bv.w,acc[3][3]);
        }
        __syncthreads();
        cur ^= 1;
    }
    if (EPI == EPI_ADD){
        #pragma unroll
        for (int i = 0; i < 4; i++){
            int m = m0 + (ty<<2) + i;
            float* op = out + (size_t)m*64 + (tx<<2);
            float4 o = *(const float4*)op;
            o.x += acc[i][0]; o.y += acc[i][1]; o.z += acc[i][2]; o.w += acc[i][3];
            *(float4*)op = o;
        }
    } else {
        // FINAL: stage v + bias + tres transposed, then coalesced NCHW write adding x
        int b = m0 >> 12, l0 = m0 & 4095;
        #pragma unroll
        for (int i = 0; i < 4; i++){
            int m = m0 + (ty<<2) + i;
            float4 tr = *(const float4*)(tres + (size_t)m*64 + (tx<<2));
            St[(tx<<2)+0][(ty<<2)+i] = acc[i][0] + tr.x + bias[(tx<<2)+0];
            St[(tx<<2)+1][(ty<<2)+i] = acc[i][1] + tr.y + bias[(tx<<2)+1];
            St[(tx<<2)+2][(ty<<2)+i] = acc[i][2] + tr.z + bias[(tx<<2)+2];
            St[(tx<<2)+3][(ty<<2)+i] = acc[i][3] + tr.w + bias[(tx<<2)+3];
        }
        __syncthreads();
        #pragma unroll
        for (int r = 0; r < 4; r++){
            int q = t + r*128;
            int n = q >> 3, cch = q & 7;
            float4 s = *(const float4*)&St[n][cch<<2];
            size_t oi = (((size_t)(b*64 + n)) << 12) + l0 + (cch<<2);
            float4 xr = *(const float4*)(xres + oi);
            s.x += xr.x; s.y += xr.y; s.z += xr.z; s.w += xr.w;
            *(float4*)(out + oi) = s;
        }
    }
}

// ------------------------- causal dwconv1d + silu -------------------------
__global__ void conv1d_kernel(const float* __restrict__ cw, const float* __restrict__ cb){
    int idx = blockIdx.x*256 + threadIdx.x;           // M*128
    int d = idx & 127, m = idx >> 7;
    int b = m >> 12, tt = m & 4095;
    float acc = cb[d];
    #pragma unroll
    for (int k = 0; k < 4; k++){
        int t2 = tt - 3 + k;
        if (t2 >= 0) acc = fmaf(cw[d*4 + k], g_xz[(size_t)((b<<12)+t2)*256 + d], acc);
    }
    float s = acc / (1.f + expf(-acc));
    g_xc[(size_t)m*128 + d] = s;
    int q = tt >> 2, r = tt & 3;
    g_xc4[(((size_t)(b*1024+q)*128 + d)<<2) + r] = s;
}

// ------------------------- scan pass 1a: per-chunk summaries (S, P) -------------------------
__global__ void __launch_bounds__(256) scan1_kernel(const float* __restrict__ Alog){
    __shared__ float Bsh[64][64];
    int dg = blockIdx.x, c = blockIdx.y, b = blockIdx.z;
    int tid = threadIdx.x, w = tid >> 5, lane = tid & 31;
    int d = dg*8 + w, n0 = lane, n1 = lane + 32;
    float A0 = -__expf(Alog[d*64 + n0]);
    float A1 = -__expf(Alog[d*64 + n1]);
    float h0 = 0.f, h1 = 0.f, sd = 0.f;
    const float4* dp4 = (const float4*)g_d4  + (size_t)b*1024*128 + d;
    const float4* up4 = (const float4*)g_xc4 + (size_t)b*1024*128 + d;
    for (int s = 0; s < 4; s++){
        int m0 = b*4096 + c*256 + s*64;
        __syncthreads();
        #pragma unroll
        for (int rep = 0; rep < 4; rep++){
            int i = rep*256 + tid; int row = i >> 4, v = i & 15;
            *(float4*)&Bsh[row][v*4] = *(const float4*)(g_Brow + (size_t)(m0+row)*64 + v*4);
        }
        __syncthreads();
        int qb = (c*256 + s*64) >> 2;
        float4 dq = dp4[(size_t)qb*128], uq = up4[(size_t)qb*128];
        for (int qi = 0; qi < 16; qi++){
            float4 dc = dq, uc = uq;
            if (qi < 15){ dq = dp4[(size_t)(qb+qi+1)*128]; uq = up4[(size_t)(qb+qi+1)*128]; }
            float dv[4], uv[4];
            *(float4*)dv = dc; *(float4*)uv = uc;
            #pragma unroll
            for (int j = 0; j < 4; j++){
                int row = qi*4 + j;
                float du = dv[j]*uv[j];
                h0 = fmaf(h0, __expf(dv[j]*A0), du*Bsh[row][n0]);
                h1 = fmaf(h1, __expf(dv[j]*A1), du*Bsh[row][n1]);
                sd += dv[j];
            }
        }
    }
    size_t base = ((size_t)((b*NCH + c)*128 + d))*64;
    g_S[base + n0] = h0;              g_S[base + n1] = h1;
    g_P[base + n0] = __expf(sd*A0);   g_P[base + n1] = __expf(sd*A1);
}

// ------------------------- scan pass 1b: combine chunk summaries -> h_init -------------------------
__global__ void scan2_kernel(){
    int wg = blockIdx.x*4 + (threadIdx.x >> 5);  // 0..255 = (b,d)
    int lane = threadIdx.x & 31;
    int b = wg >> 7, d = wg & 127;
    float h0 = 0.f, h1 = 0.f;
    for (int c = 0; c < NCH; c++){
        size_t base = ((size_t)((b*NCH + c)*128 + d))*64;
        g_Hi[base + lane]      = h0;
        g_Hi[base + 32 + lane] = h1;
        h0 = fmaf(g_P[base + lane],      h0, g_S[base + lane]);
        h1 = fmaf(g_P[base + 32 + lane], h1, g_S[base + 32 + lane]);
    }
}

// ------------------------- scan pass 2: full scan + batched 4-row reductions -------------------------
__global__ void __launch_bounds__(256) scan3_kernel(const float* __restrict__ Alog,
                                                    const float* __restrict__ Dp){
    __shared__ float Bsh[64][64];
    __shared__ float Csh[64][64];
    __shared__ float Zsh[64][8];
    int dg = blockIdx.x, c = blockIdx.y, b = blockIdx.z;
    int tid = threadIdx.x, w = tid >> 5, lane = tid & 31;
    int d = dg*8 + w, n0 = lane, n1 = lane + 32;
    float A0 = -__expf(Alog[d*64 + n0]);
    float A1 = -__expf(Alog[d*64 + n1]);
    float Dd = Dp[d];
    size_t hbase = ((size_t)((b*NCH + c)*128 + d))*64;
    float h0 = g_Hi[hbase + n0], h1 = g_Hi[hbase + n1];
    const float4* dp4 = (const float4*)g_d4  + (size_t)b*1024*128 + d;
    const float4* up4 = (const float4*)g_xc4 + (size_t)b*1024*128 + d;
    for (int s = 0; s < 4; s++){
        int m0 = b*4096 + c*256 + s*64;
        __syncthreads();
        #pragma unroll
        for (int rep = 0; rep < 4; rep++){
            int i = rep*256 + tid; int row = i >> 4, v = i & 15;
            *(float4*)&Bsh[row][v*4] = *(const float4*)(g_Brow + (size_t)(m0+row)*64 + v*4);
            *(float4*)&Csh[row][v*4] = *(const float4*)(g_Crow + (size_t)(m0+row)*64 + v*4);
        }
        if (tid < 128){
            int row = tid >> 1, hf = tid & 1;
            *(float4*)&Zsh[row][hf*4] =
                *(const float4*)(g_xz + (size_t)(m0+row)*256 + 128 + dg*8 + hf*4);
        }
        __syncthreads();
        int qb = (c*256 + s*64) >> 2;
        float4 dq = dp4[(size_t)qb*128], uq = up4[(size_t)qb*128];
        for (int qi = 0; qi < 16; qi++){
            float4 dc = dq, uc = uq;
            if (qi < 15){ dq = dp4[(size_t)(qb+qi+1)*128]; uq = up4[(size_t)(qb+qi+1)*128]; }
            float dv[4], uv[4], pr[4];
            *(float4*)dv = dc; *(float4*)uv = uc;
            #pragma unroll
            for (int j = 0; j < 4; j++){
                int row = qi*4 + j;
                float du = dv[j]*uv[j];
                h0 = fmaf(h0, __expf(dv[j]*A0), du*Bsh[row][n0]);
                h1 = fmaf(h1, __expf(dv[j]*A1), du*Bsh[row][n1]);
                pr[j] = fmaf(h0, Csh[row][n0], h1*Csh[row][n1]);
            }
            #pragma unroll
            for (int o = 16; o > 0; o >>= 1){
                pr[0] += __shfl_xor_sync(0xffffffffu, pr[0], o);
                pr[1] += __shfl_xor_sync(0xffffffffu, pr[1], o);
                pr[2] += __shfl_xor_sync(0xffffffffu, pr[2], o);
                pr[3] += __shfl_xor_sync(0xffffffffu, pr[3], o);
            }
            if (lane < 4){
                float pv  = (lane == 0) ? pr[0] : (lane == 1) ? pr[1] : (lane == 2) ? pr[2] : pr[3];
                float uvv = (lane == 0) ? uv[0] : (lane == 1) ? uv[1] : (lane == 2) ? uv[2] : uv[3];
                int row = qi*4 + lane;
                float z = Zsh[row][w];
                float sz = z / (1.f + __expf(-z));
                g_yg[(size_t)(m0+row)*128 + d] = (pv + uvv*Dd) * sz;
            }
        }
    }
}

// ------------------------- depthwise 3x3 conv + gelu, rolling 3-col window -------------------------
__global__ void __launch_bounds__(256) dwconv_kernel(const float* __restrict__ dww,
                                                     const float* __restrict__ dwb){
    int blk = blockIdx.x;                              // ((b*64 + y)*2 + xh) : 256 blocks
    int xh = blk & 1, rest = blk >> 1;
    int b = rest >> 6, y = rest & 63;
    int ch = threadIdx.x;                              // 256 channels
    float wgt[9];
    #pragma unroll
    for (int j = 0; j < 9; j++) wgt[j] = dww[ch*9 + j];
    float bb = dwb[ch];
    bool v0 = (y > 0), v2 = (y < 63);
    const float* r0 = g_h1 + (((size_t)(b<<12) + ((y-1)<<6)) << 8) + ch;
    const float* r1 = g_h1 + (((size_t)(b<<12) + ( y   <<6)) << 8) + ch;
    const float* r2 = g_h1 + (((size_t)(b<<12) + ((y+1)<<6)) << 8) + ch;
    float* outp = g_g + (((size_t)(b<<12) + (y<<6)) << 8) + ch;
    int x0 = xh << 5;
    float cp0, cp1, cp2, cc0, cc1, cc2;
    {
        int xm = x0 - 1;
        bool xv = (xm >= 0);
        cp0 = (xv && v0) ? r0[(size_t)xm << 8] : 0.f;
        cp1 =  xv        ? r1[(size_t)xm << 8] : 0.f;
        cp2 = (xv && v2) ? r2[(size_t)xm << 8] : 0.f;
        cc0 = v0 ? r0[(size_t)x0 << 8] : 0.f;
        cc1 =      r1[(size_t)x0 << 8];
        cc2 = v2 ? r2[(size_t)x0 << 8] : 0.f;
    }
    #pragma unroll 4
    for (int i = 0; i < 32; i++){
        int x = x0 + i;
        bool xv = (x + 1 < 64);
        float cn0 = (xv && v0) ? r0[(size_t)(x+1) << 8] : 0.f;
        float cn1 =  xv        ? r1[(size_t)(x+1) << 8] : 0.f;
        float cn2 = (xv && v2) ? r2[(size_t)(x+1) << 8] : 0.f;
        float acc = bb;
        acc = fmaf(wgt[0], cp0, acc); acc = fmaf(wgt[1], cc0, acc); acc = fmaf(wgt[2], cn0, acc);
        acc = fmaf(wgt[3], cp1, acc); acc = fmaf(wgt[4], cc1, acc); acc = fmaf(wgt[5], cn1, acc);
        acc = fmaf(wgt[6], cp2, acc); acc = fmaf(wgt[7], cc2, acc); acc = fmaf(wgt[8], cn2, acc);
        outp[(size_t)x << 8] = 0.5f*acc*(1.f + erff(acc*0.70710678118654752f));
        cp0 = cc0; cp1 = cc1; cp2 = cc2;
        cc0 = cn0; cc1 = cn1; cc2 = cn2;
    }
}

// ------------------------- host launch -------------------------
extern "C" void kernel_launch(void* const* d_in, const int* in_sizes, int n_in,
                              void* d_out, int out_size){
    const float* x        = (const float*)d_in[0];
    const float* conv1_w  = (const float*)d_in[1];
    const float* conv1_b  = (const float*)d_in[2];
    const float* conv2_w  = (const float*)d_in[3];
    const float* conv2_b  = (const float*)d_in[4];
    const float* ln1_w    = (const float*)d_in[5];
    const float* ln1_b    = (const float*)d_in[6];
    const float* ln2_w    = (const float*)d_in[7];
    const float* ln2_b    = (const float*)d_in[8];
    const float* in_proj  = (const float*)d_in[9];
    const float* c1d_w    = (const float*)d_in[10];
    const float* c1d_b    = (const float*)d_in[11];
    const float* xproj_w  = (const float*)d_in[12];
    const float* dtp_w    = (const float*)d_in[13];
    const float* dtp_b    = (const float*)d_in[14];
    const float* A_log    = (const float*)d_in[15];
    const float* D_param  = (const float*)d_in[16];
    const float* outp_w   = (const float*)d_in[17];
    const float* fc1_w    = (const float*)d_in[18];
    const float* fc1_b    = (const float*)d_in[19];
    const float* dw_w     = (const float*)d_in[20];
    const float* dw_b     = (const float*)d_in[21];
    const float* fc2_w    = (const float*)d_in[22];
    const float* fc2_b    = (const float*)d_in[23];
    float* out = (float*)d_out;

    float *p_t, *p_xz, *p_xc, *p_yg, *p_h1, *p_g, *p_c1, *p_w1t, *p_w2t, *p_wcat;
    cudaGetSymbolAddress((void**)&p_t,    g_t);
    cudaGetSymbolAddress((void**)&p_xz,   g_xz);
    cudaGetSymbolAddress((void**)&p_xc,   g_xc);
    cudaGetSymbolAddress((void**)&p_yg,   g_yg);
    cudaGetSymbolAddress((void**)&p_h1,   g_h1);
    cudaGetSymbolAddress((void**)&p_g,    g_g);
    cudaGetSymbolAddress((void**)&p_c1,   g_c1);
    cudaGetSymbolAddress((void**)&p_w1t,  g_w1t);
    cudaGetSymbolAddress((void**)&p_w2t,  g_w2t);
    cudaGetSymbolAddress((void**)&p_wcat, g_wcat);

    prep_kernel<<<(KCONV*CC + 255)/256, 256>>>(conv1_w, conv2_w, xproj_w, dtp_w);

    conv3_kernel<0><<<BB*HH*2, 128>>>(x,    p_w1t, conv1_b);
    conv3_kernel<1><<<BB*HH*2, 128>>>(p_c1, p_w2t, conv2_b);

    // mamba branch (LN fused into in_proj GEMM, 8x4 microtile)
    gemmln_kernel<0><<<dim3(MM/64, 4), 128>>>(p_t, in_proj, ln1_w, ln1_b, nullptr,
                                              p_xz, 256);
    conv1d_kernel<<<MM*DIN/256, 256>>>(c1d_w, c1d_b);
    gemmscan_kernel<<<dim3(MM/64, 4), 128>>>(p_xc, p_wcat, dtp_b);

    scan1_kernel<<<dim3(16, NCH, BB), 256>>>(A_log);
    scan2_kernel<<<64, 128>>>();
    scan3_kernel<<<dim3(16, NCH, BB), 256>>>(A_log, D_param);

    gemm32_kernel<EPI_ADD><<<MM/32, 128>>>(p_yg, outp_w, nullptr, p_t, 128,
                                           nullptr, nullptr);

    // FFN branch (LN fused into fc1 GEMM)
    gemmln_kernel<1><<<dim3(MM/64, 4), 128>>>(p_t, fc1_w, ln2_w, ln2_b, fc1_b,
                                              p_h1, 256);
    dwconv_kernel<<<BB*HH*2, 256>>>(dw_w, dw_b);
    gemm32_kernel<EPI_FINAL><<<MM/32, 128>>>(p_g, fc2_w, fc2_b, out, 256,
                                             x, p_t);
}